// round 16
// baseline (speedup 1.0000x reference)
#include <cuda_runtime.h>
#include <math.h>
#include <stdint.h>

// Problem constants
#define B_   2
#define L_   2048
#define D_   1024
#define H_   16
#define G_   2
#define DH_  128

// Scratch (no cudaMalloc allowed)
__device__ float g_q[(size_t)B_ * L_ * H_ * DH_];
__device__ float g_k[(size_t)B_ * L_ * G_ * DH_];
__device__ float g_v[(size_t)B_ * L_ * G_ * DH_];
__device__ float g_ctx[(size_t)B_ * L_ * H_ * DH_];
// tf32-pre-rounded inputs / weights
__device__ float g_xq[(size_t)B_ * L_ * D_];
__device__ float g_xk[(size_t)B_ * L_ * D_];
__device__ float g_xv[(size_t)B_ * L_ * D_];
__device__ float g_wq[(size_t)D_ * (H_ * DH_)];
__device__ float g_wk[(size_t)D_ * (G_ * DH_)];
__device__ float g_wv[(size_t)D_ * (G_ * DH_)];
__device__ float g_wo[(size_t)(H_ * DH_) * D_];

__device__ __forceinline__ unsigned f2tf(float x) {
    unsigned r;
    asm("cvt.rna.tf32.f32 %0, %1;" : "=r"(r) : "f"(x));
    return r;
}
__device__ __forceinline__ float tfr(float x) { return __uint_as_float(f2tf(x)); }

__device__ __forceinline__ void mma_tf32(float c[4],
    unsigned a0, unsigned a1, unsigned a2, unsigned a3,
    unsigned b0, unsigned b1)
{
    asm("mma.sync.aligned.m16n8k8.row.col.f32.tf32.tf32.f32 "
        "{%0,%1,%2,%3},{%4,%5,%6,%7},{%8,%9},{%0,%1,%2,%3};"
        : "+f"(c[0]), "+f"(c[1]), "+f"(c[2]), "+f"(c[3])
        : "r"(a0), "r"(a1), "r"(a2), "r"(a3), "r"(b0), "r"(b1));
}

__device__ __forceinline__ uint32_t smem_u32(const void* p) {
    uint32_t a;
    asm("{ .reg .u64 t; cvta.to.shared.u64 t, %1; cvt.u32.u64 %0, t; }" : "=r"(a) : "l"(p));
    return a;
}

__device__ __forceinline__ void ldsm4(unsigned& r0, unsigned& r1, unsigned& r2,
                                      unsigned& r3, uint32_t addr)
{
    asm volatile("ldmatrix.sync.aligned.m8n8.x4.shared.b16 {%0,%1,%2,%3}, [%4];"
        : "=r"(r0), "=r"(r1), "=r"(r2), "=r"(r3) : "r"(addr));
}

__device__ __forceinline__ void cp16(unsigned* smem_ptr, const float* gptr) {
    unsigned a = (unsigned)__cvta_generic_to_shared(smem_ptr);
    asm volatile("cp.async.cg.shared.global [%0], [%1], 16;" :: "r"(a), "l"(gptr));
}
#define CP_COMMIT() asm volatile("cp.async.commit_group;" ::: "memory")

// ---------------------------------------------------------------------------
// Elementwise tf32 rounding (prep)
// ---------------------------------------------------------------------------
__global__ void round4_kernel(const float* __restrict__ src, float* __restrict__ dst)
{
    size_t i = ((size_t)blockIdx.x * 256 + threadIdx.x) * 4;
    float4 v = *(const float4*)(src + i);
    float4 o = { tfr(v.x), tfr(v.y), tfr(v.z), tfr(v.w) };
    *(float4*)(dst + i) = o;
}

// ---------------------------------------------------------------------------
// TF32 GEMM with bias, 4-stage cp.async pipeline, BK=16.
// Operands pre-rounded to tf32 in gmem -> no cvt in the hot loop.
// RND: round outputs to tf32 (for q/k/v feeding flash).
// ---------------------------------------------------------------------------
#define GSTAGES 4
#define APITCH 20
#define BPITCH 136
#define AS_WORDS (128 * APITCH)
#define BS_WORDS (16 * BPITCH)
#define GS_WORDS (GSTAGES * (AS_WORDS + BS_WORDS))   // 18944 words = 75776 B

template <bool RND>
__device__ __forceinline__ void gemm_body(
    const float* __restrict__ A, const float* __restrict__ Bm,
    const float* __restrict__ bias, float* __restrict__ C,
    int N, int K, int bm, int bn, unsigned* sms)
{
    const int tid  = threadIdx.x;
    const int warp = tid >> 5, lane = tid & 31;
    const int wm = warp >> 1, wn = warp & 1;
    const int gid = lane >> 2, tig = lane & 3;

    const int ar = tid >> 2, ac = (tid & 3) << 2;
    const int br = tid >> 5, bc = (tid & 31) << 2;

    float acc[2][8][4];
#pragma unroll
    for (int mi = 0; mi < 2; ++mi)
#pragma unroll
        for (int ni = 0; ni < 8; ++ni)
#pragma unroll
            for (int r = 0; r < 4; ++r) acc[mi][ni][r] = 0.f;

    const int nst = K >> 4;

#pragma unroll
    for (int s = 0; s < GSTAGES - 1; ++s) {
        unsigned* As = sms + s * (AS_WORDS + BS_WORDS);
        unsigned* Bs = As + AS_WORDS;
        int kt = s * 16;
        cp16(As + ar * APITCH + ac,        A + (size_t)(bm + ar) * K + kt + ac);
        cp16(As + (ar + 64) * APITCH + ac, A + (size_t)(bm + ar + 64) * K + kt + ac);
        cp16(Bs + br * BPITCH + bc,        Bm + (size_t)(kt + br) * N + bn + bc);
        cp16(Bs + (br + 8) * BPITCH + bc,  Bm + (size_t)(kt + br + 8) * N + bn + bc);
        CP_COMMIT();
    }

    for (int i = 0; i < nst; ++i) {
        asm volatile("cp.async.wait_group %0;" :: "n"(GSTAGES - 2) : "memory");
        __syncthreads();

        int is = i + GSTAGES - 1;
        if (is < nst) {
            int slot = is & (GSTAGES - 1);
            unsigned* As = sms + slot * (AS_WORDS + BS_WORDS);
            unsigned* Bs = As + AS_WORDS;
            int kt = is * 16;
            cp16(As + ar * APITCH + ac,        A + (size_t)(bm + ar) * K + kt + ac);
            cp16(As + (ar + 64) * APITCH + ac, A + (size_t)(bm + ar + 64) * K + kt + ac);
            cp16(Bs + br * BPITCH + bc,        Bm + (size_t)(kt + br) * N + bn + bc);
            cp16(Bs + (br + 8) * BPITCH + bc,  Bm + (size_t)(kt + br + 8) * N + bn + bc);
        }
        CP_COMMIT();

        const int slot = i & (GSTAGES - 1);
        unsigned* As = sms + slot * (AS_WORDS + BS_WORDS);
        unsigned* Bs = As + AS_WORDS;
#pragma unroll
        for (int kk = 0; kk < 2; ++kk) {
            const int k0 = kk * 8;
            unsigned a[2][4];
#pragma unroll
            for (int mi = 0; mi < 2; ++mi) {
                int row = wm * 32 + mi * 16 + gid;
                a[mi][0] = As[row * APITCH + k0 + tig];
                a[mi][1] = As[(row + 8) * APITCH + k0 + tig];
                a[mi][2] = As[row * APITCH + k0 + tig + 4];
                a[mi][3] = As[(row + 8) * APITCH + k0 + tig + 4];
            }
#pragma unroll
            for (int ni = 0; ni < 8; ++ni) {
                int col = wn * 64 + ni * 8 + gid;
                unsigned b0 = Bs[(k0 + tig) * BPITCH + col];
                unsigned b1 = Bs[(k0 + tig + 4) * BPITCH + col];
                mma_tf32(acc[0][ni], a[0][0], a[0][1], a[0][2], a[0][3], b0, b1);
                mma_tf32(acc[1][ni], a[1][0], a[1][1], a[1][2], a[1][3], b0, b1);
            }
        }
    }

#pragma unroll
    for (int mi = 0; mi < 2; ++mi)
#pragma unroll
        for (int ni = 0; ni < 8; ++ni) {
            int row = bm + wm * 32 + mi * 16 + gid;
            int col = bn + wn * 64 + ni * 8 + 2 * tig;
            float bx = bias[col], by = bias[col + 1];
            float2 o0, o1;
            if (RND) {
                o0.x = tfr(acc[mi][ni][0] + bx); o0.y = tfr(acc[mi][ni][1] + by);
                o1.x = tfr(acc[mi][ni][2] + bx); o1.y = tfr(acc[mi][ni][3] + by);
            } else {
                o0.x = acc[mi][ni][0] + bx; o0.y = acc[mi][ni][1] + by;
                o1.x = acc[mi][ni][2] + bx; o1.y = acc[mi][ni][3] + by;
            }
            *(float2*)(C + (size_t)row * N + col) = o0;
            *(float2*)(C + (size_t)(row + 8) * N + col) = o1;
        }
}

// Fused Q/K/V projection: grid.x = 512 + 64 + 64 = 640 (outputs tf32-rounded)
__global__ void __launch_bounds__(256, 2) gemm3_kernel(
    const float* __restrict__ xq, const float* __restrict__ wq,
    const float* __restrict__ bq, float* __restrict__ pq,
    const float* __restrict__ xk, const float* __restrict__ wk,
    const float* __restrict__ bk, float* __restrict__ pk,
    const float* __restrict__ xv, const float* __restrict__ wv,
    const float* __restrict__ bv, float* __restrict__ pv)
{
    extern __shared__ unsigned gsm[];
    const int blk = blockIdx.x;
    if (blk < 512) {
        gemm_body<true>(xq, wq, bq, pq, 2048, 1024, (blk >> 4) * 128, (blk & 15) * 128, gsm);
    } else if (blk < 576) {
        int t = blk - 512;
        gemm_body<true>(xk, wk, bk, pk, 256, 1024, (t >> 1) * 128, (t & 1) * 128, gsm);
    } else {
        int t = blk - 576;
        gemm_body<true>(xv, wv, bv, pv, 256, 1024, (t >> 1) * 128, (t & 1) * 128, gsm);
    }
}

// O projection (unrounded output)
__global__ void __launch_bounds__(256, 2) gemm_o_kernel(
    const float* __restrict__ ctx, const float* __restrict__ wo,
    const float* __restrict__ bo, float* __restrict__ out)
{
    extern __shared__ unsigned gsm[];
    gemm_body<false>(ctx, wo, bo, out, 1024, 2048,
                     blockIdx.y * 128, blockIdx.x * 128, gsm);
}

// ---------------------------------------------------------------------------
// TF32 flash attention (causal, GQA). Block: 64 q rows of one head, 128 thr.
// All MMA fragments via ldmatrix:
//   S-part B from Ks[j][d] (k-major, pitch 132)
//   PV  A from Ps (pitch 68), B from transposed V tile VsT[d][j] (pitch 68,
//   3-bit XOR column swizzle -> conflict-free STS and LDSM).
// K/V pre-rounded in gmem -> raw copies, no cvt in the loop.
// ---------------------------------------------------------------------------
#define KP  132
#define VTP 68
#define PP  68
#define FS_WORDS (64 * KP + 128 * VTP + 64 * PP)   // 21504 words = 86016 B

__global__ void __launch_bounds__(128) flash_tf32_kernel(const float* __restrict__ qes)
{
    extern __shared__ unsigned sm[];
    unsigned (*Ks)[KP] = (unsigned(*)[KP])sm;
    unsigned* VsT = sm + 64 * KP;
    unsigned (*Ps)[PP] = (unsigned(*)[PP])(sm + 64 * KP + 128 * VTP);

    const int tid  = threadIdx.x;
    const int warp = tid >> 5, lane = tid & 31;
    const int gid = lane >> 2, tig = lane & 3;
    const int qt = (int)gridDim.x - 1 - (int)blockIdx.x;   // heavy tiles first
    const int bh = blockIdx.y;
    const int b = bh >> 4, h = bh & 15, g = h >> 3;

    const float scale = qes[0] * 0.08838834764831845f;  // qes / sqrt(128)

    const int d0 = (tid & 31) << 2;
    const int j0 = tid >> 5;
    const int prow = warp * 16 + gid;

    // Stage Q tile (scaled, re-rounded) through Ks, build A-fragments in regs
#pragma unroll
    for (int it = 0; it < 16; ++it) {
        int r = j0 + it * 4;
        float4 v = *(const float4*)(g_q +
            ((size_t)(b * L_ + qt * 64 + r) * H_ + h) * DH_ + d0);
        uint4 u = { f2tf(v.x * scale), f2tf(v.y * scale),
                    f2tf(v.z * scale), f2tf(v.w * scale) };
        *(uint4*)&Ks[r][d0] = u;
    }
    __syncthreads();

    unsigned aq[16][4];
#pragma unroll
    for (int kk = 0; kk < 16; ++kk) {
        aq[kk][0] = Ks[prow][kk * 8 + tig];
        aq[kk][1] = Ks[prow + 8][kk * 8 + tig];
        aq[kk][2] = Ks[prow][kk * 8 + tig + 4];
        aq[kk][3] = Ks[prow + 8][kk * 8 + tig + 4];
    }

    // ldmatrix per-lane bases
    const int t4 = lane >> 3, r8 = lane & 7;
    const uint32_t ksA = smem_u32(sm);
    const uint32_t vtA = smem_u32(VsT);
    const uint32_t psA = smem_u32(&Ps[0][0]);
    const uint32_t ks_lm = ksA + ((((t4 >> 1) * 8 + r8) * KP + (t4 & 1) * 4) << 2);
    const uint32_t ps_lm = psA + (((warp * 16 + (t4 & 1) * 8 + r8) * PP + (t4 >> 1) * 4) << 2);
    const int rbase = (t4 >> 1) * 8 + r8;       // 0..15 (n-rows within 16-row group)
    const int rb2 = rbase >> 2;
    uint32_t vt_base[2], sw34[2];
#pragma unroll
    for (int e = 0; e < 2; ++e) {
        int swz = 4 * ((4 * e + rb2) & 7);
        vt_base[e] = vtA + ((rbase * VTP + (((t4 & 1) * 4) ^ (swz & 4))) << 2);
        sw34[e] = (uint32_t)((swz & 24) << 2);   // byte-XOR for kk component
    }

    float m0 = -1e30f, m1 = -1e30f, l0 = 0.f, l1 = 0.f;
    float o[16][4];
#pragma unroll
    for (int ni = 0; ni < 16; ++ni)
#pragma unroll
        for (int r = 0; r < 4; ++r) o[ni][r] = 0.f;

    const int ntiles = qt + 1;

    for (int t = 0; t < ntiles; ++t) {
        __syncthreads();
        // K tile: raw copy (pre-rounded)
#pragma unroll
        for (int it = 0; it < 16; ++it) {
            int j = j0 + it * 4;
            *(uint4*)&Ks[j][d0] = *(const uint4*)(g_k +
                ((size_t)(b * L_ + t * 64 + j) * G_ + g) * DH_ + d0);
        }
        // V tile: transposed store with XOR swizzle (conflict-free)
#pragma unroll
        for (int it = 0; it < 16; ++it) {
            int tok = warp * 16 + (it & 3) * 4 + (lane >> 3);
            int dd  = (it >> 2) * 32 + (lane & 7) * 4;
            uint4 vv = *(const uint4*)(g_v +
                ((size_t)(b * L_ + t * 64 + tok) * G_ + g) * DH_ + dd);
            int jc = tok ^ (4 * (lane & 7));
            VsT[(dd + 0) * VTP + jc] = vv.x;
            VsT[(dd + 1) * VTP + jc] = vv.y;
            VsT[(dd + 2) * VTP + jc] = vv.z;
            VsT[(dd + 3) * VTP + jc] = vv.w;
        }
        __syncthreads();

        // S = Q @ K^T  (B-fragments via ldmatrix.x4: 2 n-tiles per op)
        float s[8][4];
#pragma unroll
        for (int ni = 0; ni < 8; ++ni)
#pragma unroll
            for (int r = 0; r < 4; ++r) s[ni][r] = 0.f;

#pragma unroll
        for (int kk = 0; kk < 16; ++kk) {
            const uint32_t kb = kk * 32;
#pragma unroll
            for (int p = 0; p < 4; ++p) {
                unsigned r0, r1, r2, r3;
                ldsm4(r0, r1, r2, r3, ks_lm + p * (16 * KP * 4) + kb);
                mma_tf32(s[2 * p],     aq[kk][0], aq[kk][1], aq[kk][2], aq[kk][3], r0, r1);
                mma_tf32(s[2 * p + 1], aq[kk][0], aq[kk][1], aq[kk][2], aq[kk][3], r2, r3);
            }
        }

        // Causal mask (diagonal tile only)
        if (t == qt) {
            const int rowg0 = qt * 64 + warp * 16 + gid;
            const int rowg1 = rowg0 + 8;
#pragma unroll
            for (int ni = 0; ni < 8; ++ni) {
                int c0 = t * 64 + ni * 8 + 2 * tig;
                if (c0 > rowg0)     s[ni][0] = -1e30f;
                if (c0 + 1 > rowg0) s[ni][1] = -1e30f;
                if (c0 > rowg1)     s[ni][2] = -1e30f;
                if (c0 + 1 > rowg1) s[ni][3] = -1e30f;
            }
        }

        // Online softmax
        float rmax0 = -1e30f, rmax1 = -1e30f;
#pragma unroll
        for (int ni = 0; ni < 8; ++ni) {
            rmax0 = fmaxf(rmax0, fmaxf(s[ni][0], s[ni][1]));
            rmax1 = fmaxf(rmax1, fmaxf(s[ni][2], s[ni][3]));
        }
        rmax0 = fmaxf(rmax0, __shfl_xor_sync(0xffffffffu, rmax0, 1));
        rmax0 = fmaxf(rmax0, __shfl_xor_sync(0xffffffffu, rmax0, 2));
        rmax1 = fmaxf(rmax1, __shfl_xor_sync(0xffffffffu, rmax1, 1));
        rmax1 = fmaxf(rmax1, __shfl_xor_sync(0xffffffffu, rmax1, 2));

        float mn0 = fmaxf(m0, rmax0), mn1 = fmaxf(m1, rmax1);
        float al0 = __expf(m0 - mn0), al1 = __expf(m1 - mn1);
        float rs0 = 0.f, rs1 = 0.f;
#pragma unroll
        for (int ni = 0; ni < 8; ++ni) {
            s[ni][0] = __expf(s[ni][0] - mn0); rs0 += s[ni][0];
            s[ni][1] = __expf(s[ni][1] - mn0); rs0 += s[ni][1];
            s[ni][2] = __expf(s[ni][2] - mn1); rs1 += s[ni][2];
            s[ni][3] = __expf(s[ni][3] - mn1); rs1 += s[ni][3];
        }
        rs0 += __shfl_xor_sync(0xffffffffu, rs0, 1);
        rs0 += __shfl_xor_sync(0xffffffffu, rs0, 2);
        rs1 += __shfl_xor_sync(0xffffffffu, rs1, 1);
        rs1 += __shfl_xor_sync(0xffffffffu, rs1, 2);
        l0 = l0 * al0 + rs0; m0 = mn0;
        l1 = l1 * al1 + rs1; m1 = mn1;

#pragma unroll
        for (int ni = 0; ni < 16; ++ni) {
            o[ni][0] *= al0; o[ni][1] *= al0;
            o[ni][2] *= al1; o[ni][3] *= al1;
        }

        // P -> smem (warp-private rows, tf32)
#pragma unroll
        for (int ni = 0; ni < 8; ++ni) {
            int pc = ni * 8 + 2 * tig;
            uint2 u0 = { f2tf(s[ni][0]), f2tf(s[ni][1]) };
            uint2 u1 = { f2tf(s[ni][2]), f2tf(s[ni][3]) };
            *(uint2*)&Ps[prow][pc]     = u0;
            *(uint2*)&Ps[prow + 8][pc] = u1;
        }
        __syncwarp();

        // O += P @ V  (A from Ps via ldmatrix, B from VsT via ldmatrix)
#pragma unroll
        for (int kk = 0; kk < 8; ++kk) {
            unsigned a0, a1, a2, a3;
            ldsm4(a0, a1, a2, a3, ps_lm + kk * 32);
#pragma unroll
            for (int p = 0; p < 8; ++p) {
                unsigned r0, r1, r2, r3;
                uint32_t addr = vt_base[p & 1] + p * (16 * VTP * 4)
                              + (((uint32_t)(kk * 32)) ^ sw34[p & 1]);
                ldsm4(r0, r1, r2, r3, addr);
                mma_tf32(o[2 * p],     a0, a1, a2, a3, r0, r1);
                mma_tf32(o[2 * p + 1], a0, a1, a2, a3, r2, r3);
            }
        }
    }

    // Epilogue: tf32-rounded O / l -> g_ctx (A operand of O-proj)
    const float inv0 = 1.f / l0, inv1 = 1.f / l1;
    const int r0 = qt * 64 + warp * 16 + gid;
    float* dst0 = g_ctx + ((size_t)(b * L_ + r0) * H_ + h) * DH_;
    float* dst1 = g_ctx + ((size_t)(b * L_ + r0 + 8) * H_ + h) * DH_;
#pragma unroll
    for (int ni = 0; ni < 16; ++ni) {
        int col = ni * 8 + 2 * tig;
        float2 v0 = { tfr(o[ni][0] * inv0), tfr(o[ni][1] * inv0) };
        float2 v1 = { tfr(o[ni][2] * inv1), tfr(o[ni][3] * inv1) };
        *(float2*)(dst0 + col) = v0;
        *(float2*)(dst1 + col) = v1;
    }
}

// ---------------------------------------------------------------------------
// Launcher
// ---------------------------------------------------------------------------
extern "C" void kernel_launch(void* const* d_in, const int* in_sizes, int n_in,
                              void* d_out, int out_size)
{
    const float* in_q = (const float*)d_in[0];
    const float* in_k = (const float*)d_in[1];
    const float* in_v = (const float*)d_in[2];
    const float* Wq   = (const float*)d_in[3];
    const float* bq   = (const float*)d_in[4];
    const float* Wk   = (const float*)d_in[5];
    const float* bk   = (const float*)d_in[6];
    const float* Wv   = (const float*)d_in[7];
    const float* bv   = (const float*)d_in[8];
    const float* Wo   = (const float*)d_in[9];
    const float* bo   = (const float*)d_in[10];
    const float* qes  = (const float*)d_in[11];
    float* out = (float*)d_out;

    float *pq, *pk, *pv, *pctx, *pxq, *pxk, *pxv, *pwq, *pwk, *pwv, *pwo;
    cudaGetSymbolAddress((void**)&pq,   g_q);
    cudaGetSymbolAddress((void**)&pk,   g_k);
    cudaGetSymbolAddress((void**)&pv,   g_v);
    cudaGetSymbolAddress((void**)&pctx, g_ctx);
    cudaGetSymbolAddress((void**)&pxq,  g_xq);
    cudaGetSymbolAddress((void**)&pxk,  g_xk);
    cudaGetSymbolAddress((void**)&pxv,  g_xv);
    cudaGetSymbolAddress((void**)&pwq,  g_wq);
    cudaGetSymbolAddress((void**)&pwk,  g_wk);
    cudaGetSymbolAddress((void**)&pwv,  g_wv);
    cudaGetSymbolAddress((void**)&pwo,  g_wo);

    // Prep: tf32-round inputs and weights (all sizes are exact multiples of 1024)
    round4_kernel<<<(B_ * L_ * D_) / 1024, 256>>>(in_q, pxq);
    round4_kernel<<<(B_ * L_ * D_) / 1024, 256>>>(in_k, pxk);
    round4_kernel<<<(B_ * L_ * D_) / 1024, 256>>>(in_v, pxv);
    round4_kernel<<<(D_ * H_ * DH_) / 1024, 256>>>(Wq, pwq);
    round4_kernel<<<(D_ * G_ * DH_) / 1024, 256>>>(Wk, pwk);
    round4_kernel<<<(D_ * G_ * DH_) / 1024, 256>>>(Wv, pwv);
    round4_kernel<<<(H_ * DH_ * D_) / 1024, 256>>>(Wo, pwo);

    const int gsmem = GS_WORDS * (int)sizeof(unsigned);   // 75776 B
    cudaFuncSetAttribute(gemm3_kernel,
                         cudaFuncAttributeMaxDynamicSharedMemorySize, gsmem);
    cudaFuncSetAttribute(gemm_o_kernel,
                         cudaFuncAttributeMaxDynamicSharedMemorySize, gsmem);

    // Fused Q/K/V projections (640 CTAs), outputs tf32-rounded
    gemm3_kernel<<<640, 256, gsmem>>>(pxq, pwq, bq, pq,
                                      pxk, pwk, bk, pk,
                                      pxv, pwv, bv, pv);

    const int fsmem = FS_WORDS * (int)sizeof(unsigned);   // 86016 B
    cudaFuncSetAttribute(flash_tf32_kernel,
                         cudaFuncAttributeMaxDynamicSharedMemorySize, fsmem);
    flash_tf32_kernel<<<dim3(L_ / 64, B_ * H_), 128, fsmem>>>(qes);

    // O projection
    gemm_o_kernel<<<dim3(D_ / 128, (B_ * L_) / 128), 256, gsmem>>>(pctx, pwo, bo, out);
}